// round 2
// baseline (speedup 1.0000x reference)
#include <cuda_runtime.h>
#include <math.h>

// ---------------- problem constants ----------------
#define N0      6000
#define NT      6085      // 1 cls + 6084 feature tokens
#define NPL     6144      // padded length for nystrom
#define PADR    59        // front zero-pad rows
#define DMODEL  1024
#define NH      8
#define DH      128
#define LM      512       // landmarks
#define LGRP    12        // tokens per landmark
#define GS      78        // ppeg grid side
#define FEAT    6084
#define INDIM   1536
#define QSCALE  0.08838834764831845f   // 128^-0.5

// ---------------- device scratch (static, no allocation) ----------------
__device__ float g_h[NT * DMODEL];
__device__ float g_x[NPL * DMODEL];
__device__ float g_qkv[NPL * 3072];
__device__ float g_ql[NH * LM * DH];
__device__ float g_kl[NH * LM * DH];
__device__ float g_a1[NH * NPL * LM];
__device__ float g_a3[NH * LM * NPL];
__device__ float g_a2[NH * LM * LM];
__device__ float g_z[NH * LM * LM];
__device__ float g_zb[NH * LM * LM];
__device__ float g_xz[NH * LM * LM];
__device__ float g_m1[NH * LM * LM];
__device__ float g_m2[NH * LM * LM];
__device__ float g_a3v[NH * LM * DH];
__device__ float g_zv[NH * LM * DH];
__device__ float g_attn[NPL * DMODEL];
__device__ float g_ny[NPL * DMODEL];
__device__ float g_gates[N0 * 3];
__device__ int   g_red[2];

// ---------------- GEMM: C = alpha * A @ B^T (+bias) ----------------
// A: M x K row-major (lda), B: N x K row-major (ldb), C: M x N (ldc)
__global__ void gemm_nt(const float* __restrict__ A, int lda, long sA,
                        const float* __restrict__ B, int ldb, long sB,
                        float* __restrict__ C, int ldc, long sC,
                        int M, int N, int K,
                        const float* __restrict__ bias, float alpha)
{
    int bz = blockIdx.z;
    A += (long)bz * sA; B += (long)bz * sB; C += (long)bz * sC;
    int row0 = blockIdx.y * 128, col0 = blockIdx.x * 128;
    __shared__ float As[16][128];
    __shared__ float Bs[16][128];
    int tid = threadIdx.x;
    int tx = tid & 15, ty = tid >> 4;
    float acc[8][8];
#pragma unroll
    for (int i = 0; i < 8; i++)
#pragma unroll
        for (int j = 0; j < 8; j++) acc[i][j] = 0.f;

    for (int kk = 0; kk < K; kk += 16) {
#pragma unroll
        for (int r = 0; r < 8; r++) {
            int p = tid + r * 256;
            int m = p >> 4, k = p & 15;
            int gm = row0 + m;
            As[k][m] = (gm < M) ? A[(long)gm * lda + kk + k] : 0.f;
        }
#pragma unroll
        for (int r = 0; r < 8; r++) {
            int p = tid + r * 256;
            int n = p >> 4, k = p & 15;
            int gn = col0 + n;
            Bs[k][n] = (gn < N) ? B[(long)gn * ldb + kk + k] : 0.f;
        }
        __syncthreads();
#pragma unroll
        for (int k = 0; k < 16; k++) {
            float4 a0 = *(const float4*)&As[k][ty * 8];
            float4 a1v = *(const float4*)&As[k][ty * 8 + 4];
            float4 b0 = *(const float4*)&Bs[k][tx * 8];
            float4 b1v = *(const float4*)&Bs[k][tx * 8 + 4];
            float ar[8] = {a0.x, a0.y, a0.z, a0.w, a1v.x, a1v.y, a1v.z, a1v.w};
            float br[8] = {b0.x, b0.y, b0.z, b0.w, b1v.x, b1v.y, b1v.z, b1v.w};
#pragma unroll
            for (int i = 0; i < 8; i++)
#pragma unroll
                for (int j = 0; j < 8; j++) acc[i][j] += ar[i] * br[j];
        }
        __syncthreads();
    }
#pragma unroll
    for (int i = 0; i < 8; i++) {
        int gm = row0 + ty * 8 + i;
        if (gm >= M) continue;
#pragma unroll
        for (int j = 0; j < 8; j++) {
            int gn = col0 + tx * 8 + j;
            if (gn >= N) continue;
            float v = alpha * acc[i][j];
            if (bias) v += bias[gn];
            C[(long)gm * ldc + gn] = v;
        }
    }
}

// ---------------- GEMM: C = alpha * A @ B ----------------
// A: M x K (lda), B: K x N row-major (ldb), C: M x N (ldc)
__global__ void gemm_nn(const float* __restrict__ A, int lda, long sA,
                        const float* __restrict__ B, int ldb, long sB,
                        float* __restrict__ C, int ldc, long sC,
                        int M, int N, int K, float alpha)
{
    int bz = blockIdx.z;
    A += (long)bz * sA; B += (long)bz * sB; C += (long)bz * sC;
    int row0 = blockIdx.y * 128, col0 = blockIdx.x * 128;
    __shared__ float As[16][128];
    __shared__ float Bs[16][128];
    int tid = threadIdx.x;
    int tx = tid & 15, ty = tid >> 4;
    float acc[8][8];
#pragma unroll
    for (int i = 0; i < 8; i++)
#pragma unroll
        for (int j = 0; j < 8; j++) acc[i][j] = 0.f;

    for (int kk = 0; kk < K; kk += 16) {
#pragma unroll
        for (int r = 0; r < 8; r++) {
            int p = tid + r * 256;
            int m = p >> 4, k = p & 15;
            int gm = row0 + m;
            As[k][m] = (gm < M) ? A[(long)gm * lda + kk + k] : 0.f;
        }
#pragma unroll
        for (int r = 0; r < 8; r++) {
            int p = tid + r * 256;
            int n = p & 127, k = p >> 7;
            int gn = col0 + n;
            Bs[k][n] = (gn < N) ? B[(long)(kk + k) * ldb + gn] : 0.f;
        }
        __syncthreads();
#pragma unroll
        for (int k = 0; k < 16; k++) {
            float4 a0 = *(const float4*)&As[k][ty * 8];
            float4 a1v = *(const float4*)&As[k][ty * 8 + 4];
            float4 b0 = *(const float4*)&Bs[k][tx * 8];
            float4 b1v = *(const float4*)&Bs[k][tx * 8 + 4];
            float ar[8] = {a0.x, a0.y, a0.z, a0.w, a1v.x, a1v.y, a1v.z, a1v.w};
            float br[8] = {b0.x, b0.y, b0.z, b0.w, b1v.x, b1v.y, b1v.z, b1v.w};
#pragma unroll
            for (int i = 0; i < 8; i++)
#pragma unroll
                for (int j = 0; j < 8; j++) acc[i][j] += ar[i] * br[j];
        }
        __syncthreads();
    }
#pragma unroll
    for (int i = 0; i < 8; i++) {
        int gm = row0 + ty * 8 + i;
        if (gm >= M) continue;
#pragma unroll
        for (int j = 0; j < 8; j++) {
            int gn = col0 + tx * 8 + j;
            if (gn >= N) continue;
            C[(long)gm * ldc + gn] = alpha * acc[i][j];
        }
    }
}

// ---------------- small kernels ----------------
__global__ void zero_kernel(float* p, long n) {
    long i = blockIdx.x * (long)blockDim.x + threadIdx.x;
    if (i < n) p[i] = 0.f;
}

// gates = softmax(data @ w_gate), per token
__global__ void gates_kernel(const float* __restrict__ data,
                             const float* __restrict__ wg,
                             float* __restrict__ gates)
{
    int n = blockIdx.x;
    const float* x = data + (long)n * INDIM;
    int t = threadIdx.x;
    float s0 = 0, s1 = 0, s2 = 0;
    for (int f = t; f < INDIM; f += 128) {
        float xv = x[f];
        s0 += xv * wg[f * 3 + 0];
        s1 += xv * wg[f * 3 + 1];
        s2 += xv * wg[f * 3 + 2];
    }
    __shared__ float sh[3][128];
    sh[0][t] = s0; sh[1][t] = s1; sh[2][t] = s2;
    __syncthreads();
    for (int o = 64; o > 0; o >>= 1) {
        if (t < o) {
            sh[0][t] += sh[0][t + o];
            sh[1][t] += sh[1][t + o];
            sh[2][t] += sh[2][t + o];
        }
        __syncthreads();
    }
    if (t == 0) {
        float l0 = sh[0][0], l1 = sh[1][0], l2 = sh[2][0];
        float mx = fmaxf(l0, fmaxf(l1, l2));
        float e0 = expf(l0 - mx), e1 = expf(l1 - mx), e2 = expf(l2 - mx);
        float inv = 1.f / (e0 + e1 + e2);
        gates[n * 3 + 0] = e0 * inv;
        gates[n * 3 + 1] = e1 * inv;
        gates[n * 3 + 2] = e2 * inv;
    }
}

// h[1+n] = sum_e gates[n][e] * relu(tmp[n][e*1024+o] + expert_b[e][o])
__global__ void moe_combine(const float* __restrict__ tmp,
                            const float* __restrict__ gates,
                            const float* __restrict__ eb)
{
    int n = blockIdx.x;
    int t = threadIdx.x;
    float g0 = gates[n * 3 + 0], g1 = gates[n * 3 + 1], g2 = gates[n * 3 + 2];
    const float* row = tmp + (long)n * 3072;
    float* hrow = g_h + (long)(1 + n) * DMODEL;
#pragma unroll
    for (int r = 0; r < 4; r++) {
        int o = t + r * 256;
        float v0 = fmaxf(row[o] + eb[o], 0.f);
        float v1 = fmaxf(row[1024 + o] + eb[1024 + o], 0.f);
        float v2 = fmaxf(row[2048 + o] + eb[2048 + o], 0.f);
        hrow[o] = g0 * v0 + g1 * v1 + g2 * v2;
    }
}

// row0 = cls; rows 6001..6084 = rows 1..84
__global__ void cls_dup_kernel(const float* __restrict__ cls) {
    int i = blockIdx.x * blockDim.x + threadIdx.x;
    if (i < DMODEL) g_h[i] = cls[i];
    int j = i - DMODEL;
    if (j >= 0 && j < 84 * DMODEL) {
        int r = j / DMODEL, c = j % DMODEL;
        g_h[(long)(6001 + r) * DMODEL + c] = g_h[(long)(1 + r) * DMODEL + c];
    }
}

// layernorm rows of src -> dst
__global__ void ln_kernel(const float* __restrict__ src, float* __restrict__ dst,
                          const float* __restrict__ gam, const float* __restrict__ bet)
{
    int row = blockIdx.x;
    const float* x = src + (long)row * DMODEL;
    float* y = dst + (long)row * DMODEL;
    int t = threadIdx.x;
    float v[4];
    float s = 0;
#pragma unroll
    for (int r = 0; r < 4; r++) { v[r] = x[t + r * 256]; s += v[r]; }
    __shared__ float sh[256];
    sh[t] = s; __syncthreads();
    for (int o = 128; o > 0; o >>= 1) { if (t < o) sh[t] += sh[t + o]; __syncthreads(); }
    float mean = sh[0] / DMODEL;
    __syncthreads();
    float q = 0;
#pragma unroll
    for (int r = 0; r < 4; r++) { float d = v[r] - mean; q += d * d; }
    sh[t] = q; __syncthreads();
    for (int o = 128; o > 0; o >>= 1) { if (t < o) sh[t] += sh[t + o]; __syncthreads(); }
    float inv = rsqrtf(sh[0] / DMODEL + 1e-5f);
#pragma unroll
    for (int r = 0; r < 4; r++) {
        int c = t + r * 256;
        y[c] = (v[r] - mean) * inv * gam[c] + bet[c];
    }
}

// scale q region of qkv
__global__ void scaleq_kernel() {
    long i = blockIdx.x * (long)blockDim.x + threadIdx.x;
    if (i < (long)NPL * DMODEL) {
        long n = i >> 10, c = i & 1023;
        g_qkv[n * 3072 + c] *= QSCALE;
    }
}

// landmarks: dst[h][i][d] = mean_{j<12} qkv[(i*12+j)*3072 + off + h*128 + d]
__global__ void landmark_kernel(float* __restrict__ dst, int off) {
    int i = blockIdx.x * blockDim.x + threadIdx.x;
    if (i >= NH * LM * DH) return;
    int d = i & 127;
    int lm = (i >> 7) & 511;
    int h = i >> 16;
    float s = 0;
    const float* base = g_qkv + (long)(lm * LGRP) * 3072 + off + h * 128 + d;
#pragma unroll
    for (int j = 0; j < LGRP; j++) s += base[(long)j * 3072];
    dst[i] = s * (1.f / LGRP);
}

// row softmax, rows x len, contiguous (ld = len)
__global__ void softmax_rows(float* __restrict__ p, int len) {
    long row = blockIdx.x;
    float* x = p + row * (long)len;
    int t = threadIdx.x;
    float mx = -1e30f;
    for (int c = t; c < len; c += 256) mx = fmaxf(mx, x[c]);
    __shared__ float sh[256];
    sh[t] = mx; __syncthreads();
    for (int o = 128; o > 0; o >>= 1) { if (t < o) sh[t] = fmaxf(sh[t], sh[t + o]); __syncthreads(); }
    mx = sh[0]; __syncthreads();
    float s = 0;
    for (int c = t; c < len; c += 256) s += expf(x[c] - mx);
    sh[t] = s; __syncthreads();
    for (int o = 128; o > 0; o >>= 1) { if (t < o) sh[t] += sh[t + o]; __syncthreads(); }
    float inv = 1.f / sh[0];
    for (int c = t; c < len; c += 256) x[c] = expf(x[c] - mx) * inv;
}

__global__ void reset_red() { g_red[0] = 0; g_red[1] = 0; }

// global max of |a2| row sums and col sums (positive values -> int-bit atomicMax ok)
__global__ void pinv_norm_kernel() {
    int idx = blockIdx.x * blockDim.x + threadIdx.x;
    if (idx < NH * LM) {
        int h = idx >> 9, i = idx & 511;
        const float* row = g_a2 + (long)h * LM * LM + (long)i * LM;
        float s = 0;
        for (int j = 0; j < LM; j++) s += fabsf(row[j]);
        atomicMax(&g_red[0], __float_as_int(s));
    } else if (idx < 2 * NH * LM) {
        int k = idx - NH * LM;
        int h = k >> 9, j = k & 511;
        const float* col = g_a2 + (long)h * LM * LM + j;
        float s = 0;
        for (int i = 0; i < LM; i++) s += fabsf(col[(long)i * LM]);
        atomicMax(&g_red[1], __float_as_int(s));
    }
}

// z0 = a2^T / (rmax * cmax)
__global__ void pinv_init_kernel() {
    long idx = blockIdx.x * (long)blockDim.x + threadIdx.x;
    if (idx >= (long)NH * LM * LM) return;
    int j = idx & 511;
    int i = (idx >> 9) & 511;
    long h = idx >> 18;
    float denom = __int_as_float(g_red[0]) * __int_as_float(g_red[1]);
    g_z[idx] = g_a2[h * LM * LM + (long)j * LM + i] / denom;
}

// out = c*I - in  (batched 512x512)
__global__ void cdiag_kernel(float c, const float* __restrict__ in, float* __restrict__ out) {
    long idx = blockIdx.x * (long)blockDim.x + threadIdx.x;
    if (idx >= (long)NH * LM * LM) return;
    int j = idx & 511;
    int i = (idx >> 9) & 511;
    out[idx] = (i == j ? c : 0.f) - in[idx];
}

// attn += depthwise seq-conv33 of v
__global__ void resconv_kernel(const float* __restrict__ rw) {
    long idx = blockIdx.x * (long)blockDim.x + threadIdx.x;
    if (idx >= (long)NPL * DMODEL) return;
    int c = idx & 1023;
    long n = idx >> 10;
    int h = c >> 7;
    float acc = 0;
#pragma unroll
    for (int t = 0; t < 33; t++) {
        long s = n + t - 16;
        if (s >= 0 && s < NPL)
            acc += g_qkv[s * 3072 + 2048 + c] * rw[h * 33 + t];
    }
    g_attn[idx] += acc;
}

// h += ny[PADR + i] for the last NT rows
__global__ void residual_kernel() {
    long idx = blockIdx.x * (long)blockDim.x + threadIdx.x;
    if (idx < (long)NT * DMODEL)
        g_h[idx] += g_ny[(long)PADR * DMODEL + idx];
}

// ppeg: out = f + dw7(f)+b7 + dw5(f)+b5 + dw3(f)+b3 (to g_ny scratch)
__global__ void ppeg_kernel(const float* __restrict__ pw7, const float* __restrict__ pb7,
                            const float* __restrict__ pw5, const float* __restrict__ pb5,
                            const float* __restrict__ pw3, const float* __restrict__ pb3)
{
    int pos = blockIdx.x;            // 0..6083
    int y = pos / GS, x = pos % GS;
    int t = threadIdx.x;
#pragma unroll
    for (int r = 0; r < 4; r++) {
        int c = t + r * 256;
        float acc = g_h[(long)(1 + pos) * DMODEL + c] + pb7[c] + pb5[c] + pb3[c];
        for (int di = -3; di <= 3; di++) {
            int sy = y + di;
            if (sy < 0 || sy >= GS) continue;
            for (int dj = -3; dj <= 3; dj++) {
                int sx = x + dj;
                if (sx < 0 || sx >= GS) continue;
                float v = g_h[(long)(1 + sy * GS + sx) * DMODEL + c];
                float w = pw7[c * 49 + (di + 3) * 7 + (dj + 3)];
                if (di >= -2 && di <= 2 && dj >= -2 && dj <= 2)
                    w += pw5[c * 25 + (di + 2) * 5 + (dj + 2)];
                if (di >= -1 && di <= 1 && dj >= -1 && dj <= 1)
                    w += pw3[c * 9 + (di + 1) * 3 + (dj + 1)];
                acc += v * w;
            }
        }
        g_ny[(long)pos * DMODEL + c] = acc;
    }
}

__global__ void ppeg_copyback() {
    long idx = blockIdx.x * (long)blockDim.x + threadIdx.x;
    if (idx < (long)FEAT * DMODEL)
        g_h[DMODEL + idx] = g_ny[idx];
}

// final: LN row 0, fc2, softmax, argmax
__global__ void final_kernel(const float* __restrict__ gam, const float* __restrict__ bet,
                             const float* __restrict__ fw, const float* __restrict__ fb,
                             float* __restrict__ out, int out_size)
{
    int t = threadIdx.x;
    float v[4];
    float s = 0;
#pragma unroll
    for (int r = 0; r < 4; r++) { v[r] = g_h[t + r * 256]; s += v[r]; }
    __shared__ float sh[256];
    sh[t] = s; __syncthreads();
    for (int o = 128; o > 0; o >>= 1) { if (t < o) sh[t] += sh[t + o]; __syncthreads(); }
    float mean = sh[0] / DMODEL;
    __syncthreads();
    float q = 0;
#pragma unroll
    for (int r = 0; r < 4; r++) { float d = v[r] - mean; q += d * d; }
    sh[t] = q; __syncthreads();
    for (int o = 128; o > 0; o >>= 1) { if (t < o) sh[t] += sh[t + o]; __syncthreads(); }
    float inv = rsqrtf(sh[0] / DMODEL + 1e-5f);
    __syncthreads();
    float d0 = 0, d1 = 0;
#pragma unroll
    for (int r = 0; r < 4; r++) {
        int c = t + r * 256;
        float ln = (v[r] - mean) * inv * gam[c] + bet[c];
        d0 += ln * fw[c];
        d1 += ln * fw[DMODEL + c];
    }
    sh[t] = d0; __syncthreads();
    for (int o = 128; o > 0; o >>= 1) { if (t < o) sh[t] += sh[t + o]; __syncthreads(); }
    d0 = sh[0]; __syncthreads();
    sh[t] = d1; __syncthreads();
    for (int o = 128; o > 0; o >>= 1) { if (t < o) sh[t] += sh[t + o]; __syncthreads(); }
    d1 = sh[0];
    if (t == 0) {
        float l0 = d0 + fb[0], l1 = d1 + fb[1];
        float mx = fmaxf(l0, l1);
        float e0 = expf(l0 - mx), e1 = expf(l1 - mx);
        float invs = 1.f / (e0 + e1);
        if (out_size > 0) out[0] = l0;
        if (out_size > 1) out[1] = l1;
        if (out_size > 2) out[2] = e0 * invs;
        if (out_size > 3) out[3] = e1 * invs;
        if (out_size > 4) out[4] = (l1 > l0) ? 1.f : 0.f;
    }
}

// ---------------- host orchestration ----------------
static dim3 ggrid(int M, int N, int batch) {
    return dim3((N + 127) / 128, (M + 127) / 128, batch);
}

static void run_nystrom(const float* ln_g, const float* ln_b, const float* qkv_w,
                        const float* out_w, const float* out_b, const float* res_w,
                        float* ph, float* px, float* pqkv, float* pql, float* pkl,
                        float* pa1, float* pa3, float* pa2, float* pz, float* pzb,
                        float* pxz, float* pm1, float* pm2, float* pa3v, float* pzv,
                        float* pattn, float* pny)
{
    const long LL = (long)LM * LM;
    // zero front pad, layernorm
    zero_kernel<<<(PADR * DMODEL + 255) / 256, 256>>>(px, (long)PADR * DMODEL);
    ln_kernel<<<NT, 256>>>(ph, px + (long)PADR * DMODEL, ln_g, ln_b);
    // qkv = x @ qkv_w^T
    gemm_nt<<<ggrid(NPL, 3072, 1), 256>>>(px, DMODEL, 0, qkv_w, DMODEL, 0,
                                          pqkv, 3072, 0, NPL, 3072, DMODEL, nullptr, 1.f);
    scaleq_kernel<<<((long)NPL * DMODEL + 255) / 256, 256>>>();
    landmark_kernel<<<(NH * LM * DH + 255) / 256, 256>>>(pql, 0);
    landmark_kernel<<<(NH * LM * DH + 255) / 256, 256>>>(pkl, 1024);
    // a1 = softmax(q @ kl^T)   [per head]
    gemm_nt<<<ggrid(NPL, LM, NH), 256>>>(pqkv, 3072, 128, pkl, DH, (long)LM * DH,
                                         pa1, LM, (long)NPL * LM, NPL, LM, DH, nullptr, 1.f);
    softmax_rows<<<NH * NPL, 256>>>(pa1, LM);
    // a2 = softmax(ql @ kl^T)
    gemm_nt<<<ggrid(LM, LM, NH), 256>>>(pql, DH, (long)LM * DH, pkl, DH, (long)LM * DH,
                                        pa2, LM, LL, LM, LM, DH, nullptr, 1.f);
    softmax_rows<<<NH * LM, 256>>>(pa2, LM);
    // a3 = softmax(ql @ k^T)
    gemm_nt<<<ggrid(LM, NPL, NH), 256>>>(pql, DH, (long)LM * DH, pqkv + 1024, 3072, 128,
                                         pa3, NPL, (long)LM * NPL, LM, NPL, DH, nullptr, 1.f);
    softmax_rows<<<NH * LM, 256>>>(pa3, NPL);
    // pinv init
    reset_red<<<1, 1>>>();
    pinv_norm_kernel<<<(2 * NH * LM + 255) / 256, 256>>>();
    pinv_init_kernel<<<((long)NH * LL + 255) / 256, 256>>>();
    // Newton-Schulz iterations
    float* zc = pz; float* zn = pzb;
    long nz = (long)NH * LL;
    for (int it = 0; it < 6; it++) {
        gemm_nn<<<ggrid(LM, LM, NH), 256>>>(pa2, LM, LL, zc, LM, LL, pxz, LM, LL, LM, LM, LM, 1.f);
        cdiag_kernel<<<(nz + 255) / 256, 256>>>(7.f, pxz, pm1);
        gemm_nn<<<ggrid(LM, LM, NH), 256>>>(pxz, LM, LL, pm1, LM, LL, pm2, LM, LL, LM, LM, LM, 1.f);
        cdiag_kernel<<<(nz + 255) / 256, 256>>>(15.f, pm2, pm2);
        gemm_nn<<<ggrid(LM, LM, NH), 256>>>(pxz, LM, LL, pm2, LM, LL, pm1, LM, LL, LM, LM, LM, 1.f);
        cdiag_kernel<<<(nz + 255) / 256, 256>>>(13.f, pm1, pm1);
        gemm_nn<<<ggrid(LM, LM, NH), 256>>>(zc, LM, LL, pm1, LM, LL, zn, LM, LL, LM, LM, LM, 0.25f);
        float* tmp = zc; zc = zn; zn = tmp;
    }
    // a3v = a3 @ v
    gemm_nn<<<ggrid(LM, DH, NH), 256>>>(pa3, NPL, (long)LM * NPL, pqkv + 2048, 3072, 128,
                                        pa3v, DH, (long)LM * DH, LM, DH, NPL, 1.f);
    // zv = z @ a3v
    gemm_nn<<<ggrid(LM, DH, NH), 256>>>(zc, LM, LL, pa3v, DH, (long)LM * DH,
                                        pzv, DH, (long)LM * DH, LM, DH, LM, 1.f);
    // attn = a1 @ zv  (columns h*128..)
    gemm_nn<<<ggrid(NPL, DH, NH), 256>>>(pa1, LM, (long)NPL * LM, pzv, DH, (long)LM * DH,
                                         pattn, DMODEL, 128, NPL, DH, LM, 1.f);
    // attn += depthwise conv(v)
    resconv_kernel<<<((long)NPL * DMODEL + 255) / 256, 256>>>(res_w);
    // out proj + bias
    gemm_nt<<<ggrid(NPL, DMODEL, 1), 256>>>(pattn, DMODEL, 0, out_w, DMODEL, 0,
                                            pny, DMODEL, 0, NPL, DMODEL, DMODEL, out_b, 1.f);
    residual_kernel<<<((long)NT * DMODEL + 255) / 256, 256>>>();
}

extern "C" void kernel_launch(void* const* d_in, const int* in_sizes, int n_in,
                              void* d_out, int out_size)
{
    // Inputs 0..10 are identical in both possible orderings.
    const float* data    = (const float*)d_in[0];
    const float* w_gate  = (const float*)d_in[1];
    const float* expw    = (const float*)d_in[2];
    const float* expb    = (const float*)d_in[3];
    const float* cls     = (const float*)d_in[4];
    const float* ln1_g   = (const float*)d_in[5];
    const float* ln1_b   = (const float*)d_in[6];
    const float* qkv1_w  = (const float*)d_in[7];
    const float* out1_w  = (const float*)d_in[8];
    const float* out1_b  = (const float*)d_in[9];
    const float* res1_w  = (const float*)d_in[10];

    // Disambiguate ordering by the size of input 11:
    //   dict order (setup_inputs): in_sizes[11] == 1024   (ln2_g)
    //   signature order:           in_sizes[11] == 50176  (pw7 = 1024*49)
    const float *ln2_g, *ln2_b, *qkv2_w, *out2_w, *out2_b, *res2_w;
    const float *pw7, *pb7, *pw5, *pb5, *pw3, *pb3;
    const float *normf_g, *normf_b, *fc2_w, *fc2_b;
    if (in_sizes[11] == DMODEL) {
        // setup_inputs() dict insertion order
        ln2_g   = (const float*)d_in[11];
        ln2_b   = (const float*)d_in[12];
        qkv2_w  = (const float*)d_in[13];
        out2_w  = (const float*)d_in[14];
        out2_b  = (const float*)d_in[15];
        res2_w  = (const float*)d_in[16];
        pw7     = (const float*)d_in[17];
        pb7     = (const float*)d_in[18];
        pw5     = (const float*)d_in[19];
        pb5     = (const float*)d_in[20];
        pw3     = (const float*)d_in[21];
        pb3     = (const float*)d_in[22];
        normf_g = (const float*)d_in[23];
        normf_b = (const float*)d_in[24];
        fc2_w   = (const float*)d_in[25];
        fc2_b   = (const float*)d_in[26];
    } else {
        // reference() signature order
        pw7     = (const float*)d_in[11];
        pb7     = (const float*)d_in[12];
        pw5     = (const float*)d_in[13];
        pb5     = (const float*)d_in[14];
        pw3     = (const float*)d_in[15];
        pb3     = (const float*)d_in[16];
        ln2_g   = (const float*)d_in[17];
        ln2_b   = (const float*)d_in[18];
        qkv2_w  = (const float*)d_in[19];
        out2_w  = (const float*)d_in[20];
        out2_b  = (const float*)d_in[21];
        res2_w  = (const float*)d_in[22];
        normf_g = (const float*)d_in[23];
        normf_b = (const float*)d_in[24];
        fc2_w   = (const float*)d_in[25];
        fc2_b   = (const float*)d_in[26];
    }
    float* out = (float*)d_out;

    void *ph, *px, *pqkv, *pql, *pkl, *pa1, *pa3, *pa2, *pz, *pzb, *pxz, *pm1, *pm2,
         *pa3v, *pzv, *pattn, *pny, *pgates;
    cudaGetSymbolAddress(&ph, g_h);
    cudaGetSymbolAddress(&px, g_x);
    cudaGetSymbolAddress(&pqkv, g_qkv);
    cudaGetSymbolAddress(&pql, g_ql);
    cudaGetSymbolAddress(&pkl, g_kl);
    cudaGetSymbolAddress(&pa1, g_a1);
    cudaGetSymbolAddress(&pa3, g_a3);
    cudaGetSymbolAddress(&pa2, g_a2);
    cudaGetSymbolAddress(&pz, g_z);
    cudaGetSymbolAddress(&pzb, g_zb);
    cudaGetSymbolAddress(&pxz, g_xz);
    cudaGetSymbolAddress(&pm1, g_m1);
    cudaGetSymbolAddress(&pm2, g_m2);
    cudaGetSymbolAddress(&pa3v, g_a3v);
    cudaGetSymbolAddress(&pzv, g_zv);
    cudaGetSymbolAddress(&pattn, g_attn);
    cudaGetSymbolAddress(&pny, g_ny);
    cudaGetSymbolAddress(&pgates, g_gates);

    // ---- MoE ----
    // tmp (reuse g_qkv): data @ expert_w^T  (expert_w viewed as (3072,1536))
    gemm_nt<<<ggrid(N0, 3072, 1), 256>>>(data, INDIM, 0, expw, INDIM, 0,
                                         (float*)pqkv, 3072, 0, N0, 3072, INDIM, nullptr, 1.f);
    gates_kernel<<<N0, 128>>>(data, w_gate, (float*)pgates);
    moe_combine<<<N0, 256>>>((const float*)pqkv, (const float*)pgates, expb);
    cls_dup_kernel<<<((84 + 1) * DMODEL + 255) / 256, 256>>>(cls);

    // ---- block 1: nystrom ----
    run_nystrom(ln1_g, ln1_b, qkv1_w, out1_w, out1_b, res1_w,
                (float*)ph, (float*)px, (float*)pqkv, (float*)pql, (float*)pkl,
                (float*)pa1, (float*)pa3, (float*)pa2, (float*)pz, (float*)pzb,
                (float*)pxz, (float*)pm1, (float*)pm2, (float*)pa3v, (float*)pzv,
                (float*)pattn, (float*)pny);

    // ---- PPEG ----
    ppeg_kernel<<<FEAT, 256>>>(pw7, pb7, pw5, pb5, pw3, pb3);
    ppeg_copyback<<<((long)FEAT * DMODEL + 255) / 256, 256>>>();

    // ---- block 2: nystrom ----
    run_nystrom(ln2_g, ln2_b, qkv2_w, out2_w, out2_b, res2_w,
                (float*)ph, (float*)px, (float*)pqkv, (float*)pql, (float*)pkl,
                (float*)pa1, (float*)pa3, (float*)pa2, (float*)pz, (float*)pzb,
                (float*)pxz, (float*)pm1, (float*)pm2, (float*)pa3v, (float*)pzv,
                (float*)pattn, (float*)pny);

    // ---- head ----
    final_kernel<<<1, 256>>>(normf_g, normf_b, fc2_w, fc2_b, out, out_size);
}

// round 3
// speedup vs baseline: 2.6420x; 2.6420x over previous
#include <cuda_runtime.h>
#include <math.h>

// ---------------- problem constants ----------------
#define N0      6000
#define NT      6085      // 1 cls + 6084 feature tokens
#define NPL     6144      // padded length for nystrom
#define PADR    59        // front zero-pad rows
#define DMODEL  1024
#define NH      8
#define DH      128
#define LM      512       // landmarks
#define LGRP    12        // tokens per landmark
#define GS      78        // ppeg grid side
#define FEAT    6084
#define INDIM   1536
#define QSCALE  0.08838834764831845f   // 128^-0.5

// ---------------- device scratch (static, no allocation) ----------------
__device__ float g_h[NT * DMODEL];
__device__ float g_x[NPL * DMODEL];
__device__ float g_qkv[NPL * 3072];
__device__ float g_ql[NH * LM * DH];
__device__ float g_kl[NH * LM * DH];
__device__ float g_a1[NH * NPL * LM];
__device__ float g_a3[NH * LM * NPL];
__device__ float g_a2[NH * LM * LM];
__device__ float g_z[NH * LM * LM];
__device__ float g_zb[NH * LM * LM];
__device__ float g_xz[NH * LM * LM];
__device__ float g_m1[NH * LM * LM];
__device__ float g_m2[NH * LM * LM];
__device__ float g_a3v[NH * LM * DH];
__device__ float g_zv[NH * LM * DH];
__device__ float g_attn[NPL * DMODEL];
__device__ float g_ny[NPL * DMODEL];
__device__ float g_gates[N0 * 3];
__device__ int   g_red[2];

// ---------------- tf32 helpers ----------------
__device__ __forceinline__ unsigned f2tf(float f) {
    unsigned u;
    asm("cvt.rna.tf32.f32 %0, %1;" : "=r"(u) : "f"(f));
    return u;
}

__device__ __forceinline__ void mma_tf32(float* c, const unsigned* a, const unsigned* b) {
    asm volatile(
        "mma.sync.aligned.m16n8k8.row.col.f32.tf32.tf32.f32 "
        "{%0,%1,%2,%3}, {%4,%5,%6,%7}, {%8,%9}, {%0,%1,%2,%3};"
        : "+f"(c[0]), "+f"(c[1]), "+f"(c[2]), "+f"(c[3])
        : "r"(a[0]), "r"(a[1]), "r"(a[2]), "r"(a[3]),
          "r"(b[0]), "r"(b[1]));
}

// ---------------- tf32 tensor-core GEMM ----------------
// C = alpha * A @ op(B) (+bias), fp32 in/out, tf32 mma, fp32 accumulate.
// A: M x K row-major (lda). transB=1: B is N x K row-major (B^T used).
// transB=0: B is K x N row-major.  Batched via blockIdx.z with strides sA/sB/sC.
// Requirements: K % 16 == 0, N % 128 == 0, lda/ldb/ldc % 4 == 0 wrt float4 loads.
#define BM 128
#define BN 128
#define BKT 16
#define SPITCH 132

__global__ __launch_bounds__(256) void gemm_tf32(
    const float* __restrict__ A, int lda, long sA,
    const float* __restrict__ B, int ldb, long sB,
    float* __restrict__ C, int ldc, long sC,
    int M, int N, int K,
    const float* __restrict__ bias, float alpha, int transB)
{
    int bz = blockIdx.z;
    A += (long)bz * sA; B += (long)bz * sB; C += (long)bz * sC;
    int row0 = blockIdx.y * BM, col0 = blockIdx.x * BN;

    __shared__ unsigned As[BKT][SPITCH];
    __shared__ unsigned Bs[BKT][SPITCH];

    int tid = threadIdx.x;
    int lane = tid & 31;
    int warp = tid >> 5;
    int warp_m = (warp >> 2) * 64;   // 2 warp-rows
    int warp_n = (warp & 3) * 32;    // 4 warp-cols

    // A loader indices: 2 x float4 per thread, along K
    int ar[2], akq[2];
#pragma unroll
    for (int i = 0; i < 2; i++) { int idx = tid + i * 256; ar[i] = idx >> 2; akq[i] = idx & 3; }
    // B loader (transB): same pattern along K; (nn): along N
    int bk[2], bnq[2];
#pragma unroll
    for (int i = 0; i < 2; i++) { int idx = tid + i * 256; bk[i] = idx >> 5; bnq[i] = idx & 31; }

    float acc[4][4][4];
#pragma unroll
    for (int i = 0; i < 4; i++)
#pragma unroll
        for (int j = 0; j < 4; j++)
#pragma unroll
            for (int r = 0; r < 4; r++) acc[i][j][r] = 0.f;

    float4 ra[2], rb[2];
    const float4 z4 = make_float4(0.f, 0.f, 0.f, 0.f);

    // initial load (kk = 0)
#pragma unroll
    for (int i = 0; i < 2; i++) {
        int gr = row0 + ar[i];
        ra[i] = (gr < M) ? *(const float4*)(A + (long)gr * lda + akq[i] * 4) : z4;
    }
    if (transB) {
#pragma unroll
        for (int i = 0; i < 2; i++) {
            int gn = col0 + ar[i];
            rb[i] = (gn < N) ? *(const float4*)(B + (long)gn * ldb + akq[i] * 4) : z4;
        }
    } else {
#pragma unroll
        for (int i = 0; i < 2; i++) {
            int gn = col0 + bnq[i] * 4;
            rb[i] = (gn < N) ? *(const float4*)(B + (long)bk[i] * ldb + gn) : z4;
        }
    }

    for (int kk = 0; kk < K; kk += BKT) {
        // store staged regs -> smem (tf32)
#pragma unroll
        for (int i = 0; i < 2; i++) {
            int kq = akq[i] * 4, m = ar[i];
            As[kq + 0][m] = f2tf(ra[i].x);
            As[kq + 1][m] = f2tf(ra[i].y);
            As[kq + 2][m] = f2tf(ra[i].z);
            As[kq + 3][m] = f2tf(ra[i].w);
        }
        if (transB) {
#pragma unroll
            for (int i = 0; i < 2; i++) {
                int kq = akq[i] * 4, n = ar[i];
                Bs[kq + 0][n] = f2tf(rb[i].x);
                Bs[kq + 1][n] = f2tf(rb[i].y);
                Bs[kq + 2][n] = f2tf(rb[i].z);
                Bs[kq + 3][n] = f2tf(rb[i].w);
            }
        } else {
#pragma unroll
            for (int i = 0; i < 2; i++) {
                int k = bk[i], n = bnq[i] * 4;
                Bs[k][n + 0] = f2tf(rb[i].x);
                Bs[k][n + 1] = f2tf(rb[i].y);
                Bs[k][n + 2] = f2tf(rb[i].z);
                Bs[k][n + 3] = f2tf(rb[i].w);
            }
        }
        __syncthreads();

        // prefetch next tile into regs (overlaps with mma below)
        int kn = kk + BKT;
        if (kn < K) {
#pragma unroll
            for (int i = 0; i < 2; i++) {
                int gr = row0 + ar[i];
                ra[i] = (gr < M) ? *(const float4*)(A + (long)gr * lda + kn + akq[i] * 4) : z4;
            }
            if (transB) {
#pragma unroll
                for (int i = 0; i < 2; i++) {
                    int gn = col0 + ar[i];
                    rb[i] = (gn < N) ? *(const float4*)(B + (long)gn * ldb + kn + akq[i] * 4) : z4;
                }
            } else {
#pragma unroll
                for (int i = 0; i < 2; i++) {
                    int gn = col0 + bnq[i] * 4;
                    rb[i] = (gn < N) ? *(const float4*)(B + (long)(kn + bk[i]) * ldb + gn) : z4;
                }
            }
        }

        // compute: 2 k-chunks of 8
#pragma unroll
        for (int kc = 0; kc < BKT; kc += 8) {
            unsigned afr[4][4];
#pragma unroll
            for (int i = 0; i < 4; i++) {
                int r = warp_m + i * 16 + (lane >> 2);
                int k = kc + (lane & 3);
                afr[i][0] = As[k][r];
                afr[i][1] = As[k][r + 8];
                afr[i][2] = As[k + 4][r];
                afr[i][3] = As[k + 4][r + 8];
            }
            unsigned bfr[4][2];
#pragma unroll
            for (int j = 0; j < 4; j++) {
                int c = warp_n + j * 8 + (lane >> 2);
                int k = kc + (lane & 3);
                bfr[j][0] = Bs[k][c];
                bfr[j][1] = Bs[k + 4][c];
            }
#pragma unroll
            for (int i = 0; i < 4; i++)
#pragma unroll
                for (int j = 0; j < 4; j++)
                    mma_tf32(acc[i][j], afr[i], bfr[j]);
        }
        __syncthreads();
    }

    // epilogue
#pragma unroll
    for (int i = 0; i < 4; i++) {
#pragma unroll
        for (int half = 0; half < 2; half++) {
            int row = row0 + warp_m + i * 16 + (lane >> 2) + 8 * half;
            if (row >= M) continue;
#pragma unroll
            for (int j = 0; j < 4; j++) {
                int col = col0 + warp_n + j * 8 + 2 * (lane & 3);
                float2 v;
                v.x = alpha * acc[i][j][half * 2 + 0];
                v.y = alpha * acc[i][j][half * 2 + 1];
                if (bias) { v.x += bias[col]; v.y += bias[col + 1]; }
                *(float2*)(C + (long)row * ldc + col) = v;
            }
        }
    }
}

// ---------------- small kernels ----------------
__global__ void zero_kernel(float* p, long n) {
    long i = blockIdx.x * (long)blockDim.x + threadIdx.x;
    if (i < n) p[i] = 0.f;
}

__global__ void gates_kernel(const float* __restrict__ data,
                             const float* __restrict__ wg,
                             float* __restrict__ gates)
{
    int n = blockIdx.x;
    const float* x = data + (long)n * INDIM;
    int t = threadIdx.x;
    float s0 = 0, s1 = 0, s2 = 0;
    for (int f = t; f < INDIM; f += 128) {
        float xv = x[f];
        s0 += xv * wg[f * 3 + 0];
        s1 += xv * wg[f * 3 + 1];
        s2 += xv * wg[f * 3 + 2];
    }
    __shared__ float sh[3][128];
    sh[0][t] = s0; sh[1][t] = s1; sh[2][t] = s2;
    __syncthreads();
    for (int o = 64; o > 0; o >>= 1) {
        if (t < o) {
            sh[0][t] += sh[0][t + o];
            sh[1][t] += sh[1][t + o];
            sh[2][t] += sh[2][t + o];
        }
        __syncthreads();
    }
    if (t == 0) {
        float l0 = sh[0][0], l1 = sh[1][0], l2 = sh[2][0];
        float mx = fmaxf(l0, fmaxf(l1, l2));
        float e0 = expf(l0 - mx), e1 = expf(l1 - mx), e2 = expf(l2 - mx);
        float inv = 1.f / (e0 + e1 + e2);
        gates[n * 3 + 0] = e0 * inv;
        gates[n * 3 + 1] = e1 * inv;
        gates[n * 3 + 2] = e2 * inv;
    }
}

__global__ void moe_combine(const float* __restrict__ tmp,
                            const float* __restrict__ gates,
                            const float* __restrict__ eb)
{
    int n = blockIdx.x;
    int t = threadIdx.x;
    float g0 = gates[n * 3 + 0], g1 = gates[n * 3 + 1], g2 = gates[n * 3 + 2];
    const float* row = tmp + (long)n * 3072;
    float* hrow = g_h + (long)(1 + n) * DMODEL;
#pragma unroll
    for (int r = 0; r < 4; r++) {
        int o = t + r * 256;
        float v0 = fmaxf(row[o] + eb[o], 0.f);
        float v1 = fmaxf(row[1024 + o] + eb[1024 + o], 0.f);
        float v2 = fmaxf(row[2048 + o] + eb[2048 + o], 0.f);
        hrow[o] = g0 * v0 + g1 * v1 + g2 * v2;
    }
}

__global__ void cls_dup_kernel(const float* __restrict__ cls) {
    int i = blockIdx.x * blockDim.x + threadIdx.x;
    if (i < DMODEL) g_h[i] = cls[i];
    int j = i - DMODEL;
    if (j >= 0 && j < 84 * DMODEL) {
        int r = j / DMODEL, c = j % DMODEL;
        g_h[(long)(6001 + r) * DMODEL + c] = g_h[(long)(1 + r) * DMODEL + c];
    }
}

__global__ void ln_kernel(const float* __restrict__ src, float* __restrict__ dst,
                          const float* __restrict__ gam, const float* __restrict__ bet)
{
    int row = blockIdx.x;
    const float* x = src + (long)row * DMODEL;
    float* y = dst + (long)row * DMODEL;
    int t = threadIdx.x;
    float v[4];
    float s = 0;
#pragma unroll
    for (int r = 0; r < 4; r++) { v[r] = x[t + r * 256]; s += v[r]; }
    __shared__ float sh[256];
    sh[t] = s; __syncthreads();
    for (int o = 128; o > 0; o >>= 1) { if (t < o) sh[t] += sh[t + o]; __syncthreads(); }
    float mean = sh[0] / DMODEL;
    __syncthreads();
    float q = 0;
#pragma unroll
    for (int r = 0; r < 4; r++) { float d = v[r] - mean; q += d * d; }
    sh[t] = q; __syncthreads();
    for (int o = 128; o > 0; o >>= 1) { if (t < o) sh[t] += sh[t + o]; __syncthreads(); }
    float inv = rsqrtf(sh[0] / DMODEL + 1e-5f);
#pragma unroll
    for (int r = 0; r < 4; r++) {
        int c = t + r * 256;
        y[c] = (v[r] - mean) * inv * gam[c] + bet[c];
    }
}

__global__ void scaleq_kernel() {
    long i = blockIdx.x * (long)blockDim.x + threadIdx.x;
    if (i < (long)NPL * DMODEL) {
        long n = i >> 10, c = i & 1023;
        g_qkv[n * 3072 + c] *= QSCALE;
    }
}

__global__ void landmark_kernel(float* __restrict__ dst, int off) {
    int i = blockIdx.x * blockDim.x + threadIdx.x;
    if (i >= NH * LM * DH) return;
    int d = i & 127;
    int lm = (i >> 7) & 511;
    int h = i >> 16;
    float s = 0;
    const float* base = g_qkv + (long)(lm * LGRP) * 3072 + off + h * 128 + d;
#pragma unroll
    for (int j = 0; j < LGRP; j++) s += base[(long)j * 3072];
    dst[i] = s * (1.f / LGRP);
}

__global__ void softmax_rows(float* __restrict__ p, int len) {
    long row = blockIdx.x;
    float* x = p + row * (long)len;
    int t = threadIdx.x;
    float mx = -1e30f;
    for (int c = t; c < len; c += 256) mx = fmaxf(mx, x[c]);
    __shared__ float sh[256];
    sh[t] = mx; __syncthreads();
    for (int o = 128; o > 0; o >>= 1) { if (t < o) sh[t] = fmaxf(sh[t], sh[t + o]); __syncthreads(); }
    mx = sh[0]; __syncthreads();
    float s = 0;
    for (int c = t; c < len; c += 256) s += expf(x[c] - mx);
    sh[t] = s; __syncthreads();
    for (int o = 128; o > 0; o >>= 1) { if (t < o) sh[t] += sh[t + o]; __syncthreads(); }
    float inv = 1.f / sh[0];
    for (int c = t; c < len; c += 256) x[c] = expf(x[c] - mx) * inv;
}

__global__ void reset_red() { g_red[0] = 0; g_red[1] = 0; }

__global__ void pinv_norm_kernel() {
    int idx = blockIdx.x * blockDim.x + threadIdx.x;
    if (idx < NH * LM) {
        int h = idx >> 9, i = idx & 511;
        const float* row = g_a2 + (long)h * LM * LM + (long)i * LM;
        float s = 0;
        for (int j = 0; j < LM; j++) s += fabsf(row[j]);
        atomicMax(&g_red[0], __float_as_int(s));
    } else if (idx < 2 * NH * LM) {
        int k = idx - NH * LM;
        int h = k >> 9, j = k & 511;
        const float* col = g_a2 + (long)h * LM * LM + j;
        float s = 0;
        for (int i = 0; i < LM; i++) s += fabsf(col[(long)i * LM]);
        atomicMax(&g_red[1], __float_as_int(s));
    }
}

__global__ void pinv_init_kernel() {
    long idx = blockIdx.x * (long)blockDim.x + threadIdx.x;
    if (idx >= (long)NH * LM * LM) return;
    int j = idx & 511;
    int i = (idx >> 9) & 511;
    long h = idx >> 18;
    float denom = __int_as_float(g_red[0]) * __int_as_float(g_red[1]);
    g_z[idx] = g_a2[h * LM * LM + (long)j * LM + i] / denom;
}

__global__ void cdiag_kernel(float c, const float* __restrict__ in, float* __restrict__ out) {
    long idx = blockIdx.x * (long)blockDim.x + threadIdx.x;
    if (idx >= (long)NH * LM * LM) return;
    int j = idx & 511;
    int i = (idx >> 9) & 511;
    out[idx] = (i == j ? c : 0.f) - in[idx];
}

__global__ void resconv_kernel(const float* __restrict__ rw) {
    long idx = blockIdx.x * (long)blockDim.x + threadIdx.x;
    if (idx >= (long)NPL * DMODEL) return;
    int c = idx & 1023;
    long n = idx >> 10;
    int h = c >> 7;
    float acc = 0;
#pragma unroll
    for (int t = 0; t < 33; t++) {
        long s = n + t - 16;
        if (s >= 0 && s < NPL)
            acc += g_qkv[s * 3072 + 2048 + c] * rw[h * 33 + t];
    }
    g_attn[idx] += acc;
}

__global__ void residual_kernel() {
    long idx = blockIdx.x * (long)blockDim.x + threadIdx.x;
    if (idx < (long)NT * DMODEL)
        g_h[idx] += g_ny[(long)PADR * DMODEL + idx];
}

__global__ void ppeg_kernel(const float* __restrict__ pw7, const float* __restrict__ pb7,
                            const float* __restrict__ pw5, const float* __restrict__ pb5,
                            const float* __restrict__ pw3, const float* __restrict__ pb3)
{
    int pos = blockIdx.x;            // 0..6083
    int y = pos / GS, x = pos % GS;
    int t = threadIdx.x;
#pragma unroll
    for (int r = 0; r < 4; r++) {
        int c = t + r * 256;
        float acc = g_h[(long)(1 + pos) * DMODEL + c] + pb7[c] + pb5[c] + pb3[c];
        for (int di = -3; di <= 3; di++) {
            int sy = y + di;
            if (sy < 0 || sy >= GS) continue;
            for (int dj = -3; dj <= 3; dj++) {
                int sx = x + dj;
                if (sx < 0 || sx >= GS) continue;
                float v = g_h[(long)(1 + sy * GS + sx) * DMODEL + c];
                float w = pw7[c * 49 + (di + 3) * 7 + (dj + 3)];
                if (di >= -2 && di <= 2 && dj >= -2 && dj <= 2)
                    w += pw5[c * 25 + (di + 2) * 5 + (dj + 2)];
                if (di >= -1 && di <= 1 && dj >= -1 && dj <= 1)
                    w += pw3[c * 9 + (di + 1) * 3 + (dj + 1)];
                acc += v * w;
            }
        }
        g_ny[(long)pos * DMODEL + c] = acc;
    }
}

__global__ void ppeg_copyback() {
    long idx = blockIdx.x * (long)blockDim.x + threadIdx.x;
    if (idx < (long)FEAT * DMODEL)
        g_h[DMODEL + idx] = g_ny[idx];
}

__global__ void final_kernel(const float* __restrict__ gam, const float* __restrict__ bet,
                             const float* __restrict__ fw, const float* __restrict__ fb,
                             float* __restrict__ out, int out_size)
{
    int t = threadIdx.x;
    float v[4];
    float s = 0;
#pragma unroll
    for (int r = 0; r < 4; r++) { v[r] = g_h[t + r * 256]; s += v[r]; }
    __shared__ float sh[256];
    sh[t] = s; __syncthreads();
    for (int o = 128; o > 0; o >>= 1) { if (t < o) sh[t] += sh[t + o]; __syncthreads(); }
    float mean = sh[0] / DMODEL;
    __syncthreads();
    float q = 0;
#pragma unroll
    for (int r = 0; r < 4; r++) { float d = v[r] - mean; q += d * d; }
    sh[t] = q; __syncthreads();
    for (int o = 128; o > 0; o >>= 1) { if (t < o) sh[t] += sh[t + o]; __syncthreads(); }
    float inv = rsqrtf(sh[0] / DMODEL + 1e-5f);
    __syncthreads();
    float d0 = 0, d1 = 0;
#pragma unroll
    for (int r = 0; r < 4; r++) {
        int c = t + r * 256;
        float ln = (v[r] - mean) * inv * gam[c] + bet[c];
        d0 += ln * fw[c];
        d1 += ln * fw[DMODEL + c];
    }
    sh[t] = d0; __syncthreads();
    for (int o = 128; o > 0; o >>= 1) { if (t < o) sh[t] += sh[t + o]; __syncthreads(); }
    d0 = sh[0]; __syncthreads();
    sh[t] = d1; __syncthreads();
    for (int o = 128; o > 0; o >>= 1) { if (t < o) sh[t] += sh[t + o]; __syncthreads(); }
    d1 = sh[0];
    if (t == 0) {
        float l0 = d0 + fb[0], l1 = d1 + fb[1];
        float mx = fmaxf(l0, l1);
        float e0 = expf(l0 - mx), e1 = expf(l1 - mx);
        float invs = 1.f / (e0 + e1);
        if (out_size > 0) out[0] = l0;
        if (out_size > 1) out[1] = l1;
        if (out_size > 2) out[2] = e0 * invs;
        if (out_size > 3) out[3] = e1 * invs;
        if (out_size > 4) out[4] = (l1 > l0) ? 1.f : 0.f;
    }
}

// ---------------- host orchestration ----------------
static dim3 ggrid(int M, int N, int batch) {
    return dim3((N + 127) / 128, (M + 127) / 128, batch);
}

static void run_nystrom(const float* ln_g, const float* ln_b, const float* qkv_w,
                        const float* out_w, const float* out_b, const float* res_w,
                        float* ph, float* px, float* pqkv, float* pql, float* pkl,
                        float* pa1, float* pa3, float* pa2, float* pz, float* pzb,
                        float* pxz, float* pm1, float* pm2, float* pa3v, float* pzv,
                        float* pattn, float* pny)
{
    const long LL = (long)LM * LM;
    zero_kernel<<<(PADR * DMODEL + 255) / 256, 256>>>(px, (long)PADR * DMODEL);
    ln_kernel<<<NT, 256>>>(ph, px + (long)PADR * DMODEL, ln_g, ln_b);
    // qkv = x @ qkv_w^T
    gemm_tf32<<<ggrid(NPL, 3072, 1), 256>>>(px, DMODEL, 0, qkv_w, DMODEL, 0,
                                            pqkv, 3072, 0, NPL, 3072, DMODEL, nullptr, 1.f, 1);
    scaleq_kernel<<<((long)NPL * DMODEL + 255) / 256, 256>>>();
    landmark_kernel<<<(NH * LM * DH + 255) / 256, 256>>>(pql, 0);
    landmark_kernel<<<(NH * LM * DH + 255) / 256, 256>>>(pkl, 1024);
    // a1 = softmax(q @ kl^T)
    gemm_tf32<<<ggrid(NPL, LM, NH), 256>>>(pqkv, 3072, 128, pkl, DH, (long)LM * DH,
                                           pa1, LM, (long)NPL * LM, NPL, LM, DH, nullptr, 1.f, 1);
    softmax_rows<<<NH * NPL, 256>>>(pa1, LM);
    // a2 = softmax(ql @ kl^T)
    gemm_tf32<<<ggrid(LM, LM, NH), 256>>>(pql, DH, (long)LM * DH, pkl, DH, (long)LM * DH,
                                          pa2, LM, LL, LM, LM, DH, nullptr, 1.f, 1);
    softmax_rows<<<NH * LM, 256>>>(pa2, LM);
    // a3 = softmax(ql @ k^T)
    gemm_tf32<<<ggrid(LM, NPL, NH), 256>>>(pql, DH, (long)LM * DH, pqkv + 1024, 3072, 128,
                                           pa3, NPL, (long)LM * NPL, LM, NPL, DH, nullptr, 1.f, 1);
    softmax_rows<<<NH * LM, 256>>>(pa3, NPL);
    // pinv init
    reset_red<<<1, 1>>>();
    pinv_norm_kernel<<<(2 * NH * LM + 255) / 256, 256>>>();
    pinv_init_kernel<<<((long)NH * LL + 255) / 256, 256>>>();
    // Newton-Schulz
    float* zc = pz; float* zn = pzb;
    long nz = (long)NH * LL;
    for (int it = 0; it < 6; it++) {
        gemm_tf32<<<ggrid(LM, LM, NH), 256>>>(pa2, LM, LL, zc, LM, LL, pxz, LM, LL, LM, LM, LM, nullptr, 1.f, 0);
        cdiag_kernel<<<(nz + 255) / 256, 256>>>(7.f, pxz, pm1);
        gemm_tf32<<<ggrid(LM, LM, NH), 256>>>(pxz, LM, LL, pm1, LM, LL, pm2, LM, LL, LM, LM, LM, nullptr, 1.f, 0);
        cdiag_kernel<<<(nz + 255) / 256, 256>>>(15.f, pm2, pm2);
        gemm_tf32<<<ggrid(LM, LM, NH), 256>>>(pxz, LM, LL, pm2, LM, LL, pm1, LM, LL, LM, LM, LM, nullptr, 1.f, 0);
        cdiag_kernel<<<(nz + 255) / 256, 256>>>(13.f, pm1, pm1);
        gemm_tf32<<<ggrid(LM, LM, NH), 256>>>(zc, LM, LL, pm1, LM, LL, zn, LM, LL, LM, LM, LM, nullptr, 0.25f, 0);
        float* tmp = zc; zc = zn; zn = tmp;
    }
    // a3v = a3 @ v
    gemm_tf32<<<ggrid(LM, DH, NH), 256>>>(pa3, NPL, (long)LM * NPL, pqkv + 2048, 3072, 128,
                                          pa3v, DH, (long)LM * DH, LM, DH, NPL, nullptr, 1.f, 0);
    // zv = z @ a3v
    gemm_tf32<<<ggrid(LM, DH, NH), 256>>>(zc, LM, LL, pa3v, DH, (long)LM * DH,
                                          pzv, DH, (long)LM * DH, LM, DH, LM, nullptr, 1.f, 0);
    // attn = a1 @ zv
    gemm_tf32<<<ggrid(NPL, DH, NH), 256>>>(pa1, LM, (long)NPL * LM, pzv, DH, (long)LM * DH,
                                           pattn, DMODEL, 128, NPL, DH, LM, nullptr, 1.f, 0);
    resconv_kernel<<<((long)NPL * DMODEL + 255) / 256, 256>>>(res_w);
    // out proj + bias
    gemm_tf32<<<ggrid(NPL, DMODEL, 1), 256>>>(pattn, DMODEL, 0, out_w, DMODEL, 0,
                                              pny, DMODEL, 0, NPL, DMODEL, DMODEL, out_b, 1.f, 1);
    residual_kernel<<<((long)NT * DMODEL + 255) / 256, 256>>>();
}

extern "C" void kernel_launch(void* const* d_in, const int* in_sizes, int n_in,
                              void* d_out, int out_size)
{
    const float* data    = (const float*)d_in[0];
    const float* w_gate  = (const float*)d_in[1];
    const float* expw    = (const float*)d_in[2];
    const float* expb    = (const float*)d_in[3];
    const float* cls     = (const float*)d_in[4];
    const float* ln1_g   = (const float*)d_in[5];
    const float* ln1_b   = (const float*)d_in[6];
    const float* qkv1_w  = (const float*)d_in[7];
    const float* out1_w  = (const float*)d_in[8];
    const float* out1_b  = (const float*)d_in[9];
    const float* res1_w  = (const float*)d_in[10];

    const float *ln2_g, *ln2_b, *qkv2_w, *out2_w, *out2_b, *res2_w;
    const float *pw7, *pb7, *pw5, *pb5, *pw3, *pb3;
    const float *normf_g, *normf_b, *fc2_w, *fc2_b;
    if (in_sizes[11] == DMODEL) {
        ln2_g   = (const float*)d_in[11];
        ln2_b   = (const float*)d_in[12];
        qkv2_w  = (const float*)d_in[13];
        out2_w  = (const float*)d_in[14];
        out2_b  = (const float*)d_in[15];
        res2_w  = (const float*)d_in[16];
        pw7     = (const float*)d_in[17];
        pb7     = (const float*)d_in[18];
        pw5     = (const float*)d_in[19];
        pb5     = (const float*)d_in[20];
        pw3     = (const float*)d_in[21];
        pb3     = (const float*)d_in[22];
        normf_g = (const float*)d_in[23];
        normf_b = (const float*)d_in[24];
        fc2_w   = (const float*)d_in[25];
        fc2_b   = (const float*)d_in[26];
    } else {
        pw7     = (const float*)d_in[11];
        pb7     = (const float*)d_in[12];
        pw5     = (const float*)d_in[13];
        pb5     = (const float*)d_in[14];
        pw3     = (const float*)d_in[15];
        pb3     = (const float*)d_in[16];
        ln2_g   = (const float*)d_in[17];
        ln2_b   = (const float*)d_in[18];
        qkv2_w  = (const float*)d_in[19];
        out2_w  = (const float*)d_in[20];
        out2_b  = (const float*)d_in[21];
        res2_w  = (const float*)d_in[22];
        normf_g = (const float*)d_in[23];
        normf_b = (const float*)d_in[24];
        fc2_w   = (const float*)d_in[25];
        fc2_b   = (const float*)d_in[26];
    }
    float* out = (float*)d_out;

    void *ph, *px, *pqkv, *pql, *pkl, *pa1, *pa3, *pa2, *pz, *pzb, *pxz, *pm1, *pm2,
         *pa3v, *pzv, *pattn, *pny, *pgates;
    cudaGetSymbolAddress(&ph, g_h);
    cudaGetSymbolAddress(&px, g_x);
    cudaGetSymbolAddress(&pqkv, g_qkv);
    cudaGetSymbolAddress(&pql, g_ql);
    cudaGetSymbolAddress(&pkl, g_kl);
    cudaGetSymbolAddress(&pa1, g_a1);
    cudaGetSymbolAddress(&pa3, g_a3);
    cudaGetSymbolAddress(&pa2, g_a2);
    cudaGetSymbolAddress(&pz, g_z);
    cudaGetSymbolAddress(&pzb, g_zb);
    cudaGetSymbolAddress(&pxz, g_xz);
    cudaGetSymbolAddress(&pm1, g_m1);
    cudaGetSymbolAddress(&pm2, g_m2);
    cudaGetSymbolAddress(&pa3v, g_a3v);
    cudaGetSymbolAddress(&pzv, g_zv);
    cudaGetSymbolAddress(&pattn, g_attn);
    cudaGetSymbolAddress(&pny, g_ny);
    cudaGetSymbolAddress(&pgates, g_gates);

    // ---- MoE ----
    gemm_tf32<<<ggrid(N0, 3072, 1), 256>>>(data, INDIM, 0, expw, INDIM, 0,
                                           (float*)pqkv, 3072, 0, N0, 3072, INDIM, nullptr, 1.f, 1);
    gates_kernel<<<N0, 128>>>(data, w_gate, (float*)pgates);
    moe_combine<<<N0, 256>>>((const float*)pqkv, (const float*)pgates, expb);
    cls_dup_kernel<<<((84 + 1) * DMODEL + 255) / 256, 256>>>(cls);

    // ---- block 1 ----
    run_nystrom(ln1_g, ln1_b, qkv1_w, out1_w, out1_b, res1_w,
                (float*)ph, (float*)px, (float*)pqkv, (float*)pql, (float*)pkl,
                (float*)pa1, (float*)pa3, (float*)pa2, (float*)pz, (float*)pzb,
                (float*)pxz, (float*)pm1, (float*)pm2, (float*)pa3v, (float*)pzv,
                (float*)pattn, (float*)pny);

    // ---- PPEG ----
    ppeg_kernel<<<FEAT, 256>>>(pw7, pb7, pw5, pb5, pw3, pb3);
    ppeg_copyback<<<((long)FEAT * DMODEL + 255) / 256, 256>>>();

    // ---- block 2 ----
    run_nystrom(ln2_g, ln2_b, qkv2_w, out2_w, out2_b, res2_w,
                (float*)ph, (float*)px, (float*)pqkv, (float*)pql, (float*)pkl,
                (float*)pa1, (float*)pa3, (float*)pa2, (float*)pz, (float*)pzb,
                (float*)pxz, (float*)pm1, (float*)pm2, (float*)pa3v, (float*)pzv,
                (float*)pattn, (float*)pny);

    // ---- head ----
    final_kernel<<<1, 256>>>(normf_g, normf_b, fc2_w, fc2_b, out, out_size);
}